// round 3
// baseline (speedup 1.0000x reference)
#include <cuda_runtime.h>
#include <math.h>

// Problem constants
#define Bn    16
#define CINc  8
#define SEQ   32
#define Hh    128
#define Ww    128
#define COUTc 8
#define ZC    32   // 4*COUT gate channels
#define CTOT  16   // CIN + COUT

// Tiling
#define TW 32
#define TH 8
#define NTHREADS 128      // 16 x 8 threads, each owning 2 x-adjacent pixels
#define HALO_W (TW + 2)   // 34
#define HALO_H (TH + 2)   // 10

#define STATE_ELEMS (Bn * COUTc * Hh * Ww)

// Recurrent state. g_h is DOUBLE-BUFFERED: halo reads cross block boundaries,
// so reading (t-1)-state and writing t-state must not alias within one launch.
__device__ float g_h[2][STATE_ELEMS];
__device__ float g_c[STATE_ELEMS];

__device__ __forceinline__ float sigf(float x) {
    return 1.0f / (1.0f + expf(-x));
}

template <bool FIRST>
__global__ __launch_bounds__(NTHREADS)
void convlstm_step(const float* __restrict__ X,
                   const float* __restrict__ Wc,
                   const float* __restrict__ bc,
                   float* __restrict__ out,
                   int t)
{
    // weights laid out [tap(cin*9+ky*3+kx)][oc] so oc-inner loop is contiguous
    __shared__ float s_w[CTOT * 9][ZC];                 // 18432 B
    __shared__ float s_in[CTOT][HALO_H][HALO_W];        // 21760 B
    __shared__ float s_b[ZC];

    const float* __restrict__ h_prev = g_h[(t + 1) & 1];  // state from t-1
    float* __restrict__ h_cur = g_h[t & 1];               // state for t

    const int tid = threadIdx.x;
    const int tx = tid & 15;          // 0..15 -> pixel pair column
    const int ty = tid >> 4;          // 0..7
    const int bxi = blockIdx.x, byi = blockIdx.y, b = blockIdx.z;
    const int x0 = bxi * TW;
    const int y0 = byi * TH;

    // ---- load weights: Wc[oc][ic][ky][kx] linear index = oc*144 + k ----
    for (int i = tid; i < CTOT * 9 * ZC; i += NTHREADS) {
        int oc = i / (CTOT * 9);
        int k  = i - oc * (CTOT * 9);
        s_w[k][oc] = Wc[i];
    }
    if (tid < ZC) s_b[tid] = bc[tid];

    // ---- load input tile with halo: channels 0..7 from X_t, 8..15 from h_{t-1} ----
    float* s_in_flat = &s_in[0][0][0];
    const int tile_elems = CTOT * HALO_H * HALO_W;
    for (int i = tid; i < tile_elems; i += NTHREADS) {
        int c   = i / (HALO_H * HALO_W);
        int rem = i - c * (HALO_H * HALO_W);
        int r   = rem / HALO_W;
        int col = rem - r * HALO_W;
        int gy = y0 + r - 1;
        int gxl = x0 + col - 1;
        float v = 0.0f;
        if (gy >= 0 && gy < Hh && gxl >= 0 && gxl < Ww) {
            if (c < CINc) {
                v = X[(((size_t)(b * CINc + c) * SEQ + t) * Hh + gy) * Ww + gxl];
            } else if (!FIRST) {
                v = h_prev[((size_t)(b * COUTc + (c - CINc)) * Hh + gy) * Ww + gxl];
            }
        }
        s_in_flat[i] = v;
    }
    __syncthreads();

    // ---- accumulate: 2 pixels per thread, 32 gate channels each ----
    float acc0[ZC], acc1[ZC];
#pragma unroll
    for (int oc = 0; oc < ZC; oc++) {
        float bv = s_b[oc];
        acc0[oc] = bv;
        acc1[oc] = bv;
    }

    const int px = tx * 2;  // tile-local x of pixel 0

#pragma unroll 1
    for (int c = 0; c < CTOT; c++) {
#pragma unroll
        for (int ky = 0; ky < 3; ky++) {
            const float* row = &s_in[c][ty + ky][px];
            float v0 = row[0], v1 = row[1], v2 = row[2], v3 = row[3];
#pragma unroll
            for (int kx = 0; kx < 3; kx++) {
                float a = (kx == 0) ? v0 : ((kx == 1) ? v1 : v2);
                float d = (kx == 0) ? v1 : ((kx == 1) ? v2 : v3);
                const float* wp = s_w[c * 9 + ky * 3 + kx];
#pragma unroll
                for (int oc = 0; oc < ZC; oc++) {
                    float w = wp[oc];
                    acc0[oc] = fmaf(a, w, acc0[oc]);
                    acc1[oc] = fmaf(d, w, acc1[oc]);
                }
            }
        }
    }

    // ---- gates + state update + output write (float2, coalesced) ----
    const int gx = x0 + px;      // even
    const int gy = y0 + ty;
    const size_t pix = (size_t)gy * Ww + gx;

#pragma unroll
    for (int k = 0; k < COUTc; k++) {
        float i0 = sigf(acc0[k]),          i1 = sigf(acc1[k]);
        float f0 = sigf(acc0[k + 8]),      f1 = sigf(acc1[k + 8]);
        float g0 = tanhf(acc0[k + 16]),    g1 = tanhf(acc1[k + 16]);
        float o0 = sigf(acc0[k + 24]),     o1 = sigf(acc1[k + 24]);

        size_t sidx = (size_t)(b * COUTc + k) * (Hh * Ww) + pix;
        float c0p = 0.0f, c1p = 0.0f;
        if (!FIRST) {
            float2 cp = *reinterpret_cast<const float2*>(&g_c[sidx]);
            c0p = cp.x; c1p = cp.y;
        }
        float cn0 = f0 * c0p + i0 * g0;
        float cn1 = f1 * c1p + i1 * g1;
        float hn0 = o0 * tanhf(cn0);
        float hn1 = o1 * tanhf(cn1);

        *reinterpret_cast<float2*>(&g_c[sidx]) = make_float2(cn0, cn1);
        *reinterpret_cast<float2*>(&h_cur[sidx]) = make_float2(hn0, hn1);

        size_t oidx = ((size_t)(b * COUTc + k) * SEQ + t) * (Hh * Ww) + pix;
        *reinterpret_cast<float2*>(&out[oidx]) = make_float2(hn0, hn1);
    }
}

extern "C" void kernel_launch(void* const* d_in, const int* in_sizes, int n_in,
                              void* d_out, int out_size)
{
    const float* X  = (const float*)d_in[0];
    const float* Wc = (const float*)d_in[1];
    const float* bc = (const float*)d_in[2];
    float* out = (float*)d_out;

    dim3 grid(Ww / TW, Hh / TH, Bn);   // (4, 16, 16) = 1024 blocks
    convlstm_step<true><<<grid, NTHREADS>>>(X, Wc, bc, out, 0);
    for (int t = 1; t < SEQ; t++) {
        convlstm_step<false><<<grid, NTHREADS>>>(X, Wc, bc, out, t);
    }
}

// round 4
// speedup vs baseline: 1.2743x; 1.2743x over previous
#include <cuda_runtime.h>
#include <math.h>

// Problem constants
#define Bn    16
#define CINc  8
#define SEQ   32
#define Hh    128
#define Ww    128
#define COUTc 8
#define ZC    32   // 4*COUT gate channels
#define CTOT  16   // CIN + COUT

// Tiling
#define TW 32
#define TH 8
#define NTHREADS 128      // 16 x 8 threads, each owning 2 x-adjacent pixels
#define HALO_W (TW + 2)   // 34
#define HALO_H (TH + 2)   // 10

#define STATE_ELEMS (Bn * COUTc * Hh * Ww)

// Recurrent state. g_h is DOUBLE-BUFFERED: halo reads cross block boundaries,
// so reading (t-1)-state and writing t-state must not alias within one launch.
__device__ float g_h[2][STATE_ELEMS];
__device__ float g_c[STATE_ELEMS];

typedef unsigned long long u64;

__device__ __forceinline__ u64 pack2(float x) {
    u64 r; asm("mov.b64 %0, {%1, %1};" : "=l"(r) : "f"(x)); return r;
}
__device__ __forceinline__ void fma2(u64& d, u64 a, u64 b, u64 c) {
    asm("fma.rn.f32x2 %0, %1, %2, %3;" : "=l"(d) : "l"(a), "l"(b), "l"(c));
}
__device__ __forceinline__ float f32x2_lo(u64 v) {
    float lo, hi; asm("mov.b64 {%0, %1}, %2;" : "=f"(lo), "=f"(hi) : "l"(v)); return lo;
}
__device__ __forceinline__ float f32x2_hi(u64 v) {
    float lo, hi; asm("mov.b64 {%0, %1}, %2;" : "=f"(lo), "=f"(hi) : "l"(v)); return hi;
}

// Fast gates: __expf is ~2ulp; absolute error ~1e-7 — verified in R1/R2 that
// transcendental choice does not move rel_err at the 1e-6 level.
__device__ __forceinline__ float sigf(float x) {
    return __fdividef(1.0f, 1.0f + __expf(-x));
}
__device__ __forceinline__ float tanhfast(float x) {
    return __fdividef(2.0f, 1.0f + __expf(-2.0f * x)) - 1.0f;
}

template <bool FIRST>
__global__ __launch_bounds__(NTHREADS, 5)
void convlstm_step(const float* __restrict__ X,
                   const float* __restrict__ Wc,
                   const float* __restrict__ bc,
                   float* __restrict__ out,
                   int t)
{
    // weights laid out [tap(cin*9+ky*3+kx)][oc]; oc-contiguous, so a u64 read
    // is the (w[oc], w[oc+1]) f32x2 operand directly. Rows are 128B-aligned.
    __shared__ __align__(16) float s_w[CTOT * 9][ZC];      // 18432 B
    __shared__ __align__(16) float s_in[CTOT][HALO_H][HALO_W]; // 21760 B
    __shared__ __align__(16) float s_b[ZC];

    const float* __restrict__ h_prev = g_h[(t + 1) & 1];  // state from t-1
    float* __restrict__ h_cur = g_h[t & 1];               // state for t

    const int tid = threadIdx.x;
    const int tx = tid & 15;          // 0..15 -> pixel pair column
    const int ty = tid >> 4;          // 0..7
    const int bxi = blockIdx.x, byi = blockIdx.y, b = blockIdx.z;
    const int x0 = bxi * TW;
    const int y0 = byi * TH;

    // ---- load weights: Wc[oc][ic][ky][kx] linear index = oc*144 + k ----
    for (int i = tid; i < CTOT * 9 * ZC; i += NTHREADS) {
        int oc = i / (CTOT * 9);
        int k  = i - oc * (CTOT * 9);
        s_w[k][oc] = Wc[i];
    }
    if (tid < ZC) s_b[tid] = bc[tid];

    // ---- load input tile with halo: channels 0..7 from X_t, 8..15 from h_{t-1} ----
    float* s_in_flat = &s_in[0][0][0];
    const int tile_elems = CTOT * HALO_H * HALO_W;
    for (int i = tid; i < tile_elems; i += NTHREADS) {
        int c   = i / (HALO_H * HALO_W);
        int rem = i - c * (HALO_H * HALO_W);
        int r   = rem / HALO_W;
        int col = rem - r * HALO_W;
        int gy = y0 + r - 1;
        int gxl = x0 + col - 1;
        float v = 0.0f;
        if (gy >= 0 && gy < Hh && gxl >= 0 && gxl < Ww) {
            if (c < CINc) {
                v = X[(((size_t)(b * CINc + c) * SEQ + t) * Hh + gy) * Ww + gxl];
            } else if (!FIRST) {
                v = h_prev[((size_t)(b * COUTc + (c - CINc)) * Hh + gy) * Ww + gxl];
            }
        }
        s_in_flat[i] = v;
    }
    __syncthreads();

    // ---- accumulate: 2 pixels x 32 gate channels as 16 f32x2 pairs each ----
    u64 acc0[ZC / 2], acc1[ZC / 2];
    const u64* s_b64 = reinterpret_cast<const u64*>(s_b);
#pragma unroll
    for (int j = 0; j < ZC / 2; j++) {
        u64 bp = s_b64[j];
        acc0[j] = bp;
        acc1[j] = bp;
    }

    const int px = tx * 2;  // tile-local x of pixel 0

#pragma unroll 1
    for (int c = 0; c < CTOT; c++) {
#pragma unroll
        for (int ky = 0; ky < 3; ky++) {
            const float* row = &s_in[c][ty + ky][px];
            float v0 = row[0], v1 = row[1], v2 = row[2], v3 = row[3];
            const u64* wrow = reinterpret_cast<const u64*>(&s_w[c * 9 + ky * 3][0]);
#pragma unroll
            for (int kx = 0; kx < 3; kx++) {
                float a = (kx == 0) ? v0 : ((kx == 1) ? v1 : v2);
                float d = (kx == 0) ? v1 : ((kx == 1) ? v2 : v3);
                u64 pa = pack2(a);
                u64 pd = pack2(d);
                const u64* w = wrow + kx * (ZC / 2);
#pragma unroll
                for (int j = 0; j < ZC / 2; j++) {
                    u64 wv = w[j];
                    fma2(acc0[j], pa, wv, acc0[j]);
                    fma2(acc1[j], pd, wv, acc1[j]);
                }
            }
        }
    }

    // ---- gates + state update + output write (float2, coalesced) ----
    const int gx = x0 + px;      // even
    const int gy = y0 + ty;
    const size_t pix = (size_t)gy * Ww + gx;

    // gate channel oc -> pair index oc>>1, half oc&1.
    // i: oc k (pair k/2), f: k+8 (pair k/2+4), g: k+16 (pair k/2+8), o: k+24 (pair k/2+12)
#pragma unroll
    for (int k = 0; k < COUTc; k++) {
        const int j = k >> 1;
        const bool hi = (k & 1) != 0;
        float zi0 = hi ? f32x2_hi(acc0[j])      : f32x2_lo(acc0[j]);
        float zi1 = hi ? f32x2_hi(acc1[j])      : f32x2_lo(acc1[j]);
        float zf0 = hi ? f32x2_hi(acc0[j + 4])  : f32x2_lo(acc0[j + 4]);
        float zf1 = hi ? f32x2_hi(acc1[j + 4])  : f32x2_lo(acc1[j + 4]);
        float zg0 = hi ? f32x2_hi(acc0[j + 8])  : f32x2_lo(acc0[j + 8]);
        float zg1 = hi ? f32x2_hi(acc1[j + 8])  : f32x2_lo(acc1[j + 8]);
        float zo0 = hi ? f32x2_hi(acc0[j + 12]) : f32x2_lo(acc0[j + 12]);
        float zo1 = hi ? f32x2_hi(acc1[j + 12]) : f32x2_lo(acc1[j + 12]);

        float i0 = sigf(zi0),      i1 = sigf(zi1);
        float f0 = sigf(zf0),      f1 = sigf(zf1);
        float g0 = tanhfast(zg0),  g1 = tanhfast(zg1);
        float o0 = sigf(zo0),      o1 = sigf(zo1);

        size_t sidx = (size_t)(b * COUTc + k) * (Hh * Ww) + pix;
        float c0p = 0.0f, c1p = 0.0f;
        if (!FIRST) {
            float2 cp = *reinterpret_cast<const float2*>(&g_c[sidx]);
            c0p = cp.x; c1p = cp.y;
        }
        float cn0 = f0 * c0p + i0 * g0;
        float cn1 = f1 * c1p + i1 * g1;
        float hn0 = o0 * tanhfast(cn0);
        float hn1 = o1 * tanhfast(cn1);

        *reinterpret_cast<float2*>(&g_c[sidx]) = make_float2(cn0, cn1);
        *reinterpret_cast<float2*>(&h_cur[sidx]) = make_float2(hn0, hn1);

        size_t oidx = ((size_t)(b * COUTc + k) * SEQ + t) * (Hh * Ww) + pix;
        *reinterpret_cast<float2*>(&out[oidx]) = make_float2(hn0, hn1);
    }
}

extern "C" void kernel_launch(void* const* d_in, const int* in_sizes, int n_in,
                              void* d_out, int out_size)
{
    const float* X  = (const float*)d_in[0];
    const float* Wc = (const float*)d_in[1];
    const float* bc = (const float*)d_in[2];
    float* out = (float*)d_out;

    dim3 grid(Ww / TW, Hh / TH, Bn);   // (4, 16, 16) = 1024 blocks
    convlstm_step<true><<<grid, NTHREADS>>>(X, Wc, bc, out, 0);
    for (int t = 1; t < SEQ; t++) {
        convlstm_step<false><<<grid, NTHREADS>>>(X, Wc, bc, out, t);
    }
}

// round 5
// speedup vs baseline: 1.2764x; 1.0017x over previous
#include <cuda_runtime.h>
#include <math.h>

// Problem constants
#define Bn    16
#define CINc  8
#define SEQ   32
#define Hh    128
#define Ww    128
#define COUTc 8
#define ZC    32   // 4*COUT gate channels
#define CTOT  16   // CIN + COUT

// Tiling: 32x8 tile, 128 threads; thread = 4 x-adjacent pixels x 16 gate-ch
#define TW 32
#define TH 8
#define NTHREADS 128
#define HALO_W 34
#define HALO_WP 36        // padded so each row is 144B = 16B-aligned
#define HALO_H (TH + 2)   // 10

#define STATE_ELEMS (Bn * COUTc * Hh * Ww)

// Recurrent state. g_h is DOUBLE-BUFFERED: halo reads cross block boundaries,
// so reading (t-1)-state and writing t-state must not alias within one launch.
__device__ float g_h[2][STATE_ELEMS];
__device__ float g_c[STATE_ELEMS];

typedef unsigned long long u64;

__device__ __forceinline__ u64 pack2(float x) {
    u64 r; asm("mov.b64 %0, {%1, %1};" : "=l"(r) : "f"(x)); return r;
}
__device__ __forceinline__ void fma2(u64& d, u64 a, u64 b, u64 c) {
    asm("fma.rn.f32x2 %0, %1, %2, %3;" : "=l"(d) : "l"(a), "l"(b), "l"(c));
}
__device__ __forceinline__ float xlo(u64 v) {
    float lo, hi; asm("mov.b64 {%0, %1}, %2;" : "=f"(lo), "=f"(hi) : "l"(v)); return lo;
}
__device__ __forceinline__ float xhi(u64 v) {
    float lo, hi; asm("mov.b64 {%0, %1}, %2;" : "=f"(lo), "=f"(hi) : "l"(v)); return hi;
}

// Fast gates: verified in R1/R2 that transcendental choice doesn't move
// rel_err at the 1e-6 level (error was structural, now fixed).
__device__ __forceinline__ float sigf(float x) {
    return __fdividef(1.0f, 1.0f + __expf(-x));
}
__device__ __forceinline__ float tanhfast(float x) {
    return __fdividef(2.0f, 1.0f + __expf(-2.0f * x)) - 1.0f;
}

template <bool FIRST>
__global__ __launch_bounds__(NTHREADS, 5)
void convlstm_step(const float* __restrict__ X,
                   const float* __restrict__ Wc,
                   const float* __restrict__ bc,
                   float* __restrict__ out,
                   int t)
{
    // weights [tap][oc] (oc contiguous, rows 128B): LDS.128 = 2 oc-pairs
    __shared__ __align__(16) float s_w[CTOT * 9][ZC];          // 18432 B
    __shared__ __align__(16) float s_in[CTOT][HALO_H][HALO_WP];// 23040 B
    __shared__ __align__(16) float s_b[ZC];

    const float* __restrict__ h_prev = g_h[(t + 1) & 1];
    float* __restrict__ h_cur = g_h[t & 1];

    const int tid = threadIdx.x;
    const int tx = tid & 7;           // 0..7 -> 4-pixel group column
    const int hf = (tid >> 3) & 1;    // 0/1  -> cout-channel half
    const int ty = tid >> 4;          // 0..7
    const int bxi = blockIdx.x, byi = blockIdx.y, b = blockIdx.z;
    const int x0 = bxi * TW;
    const int y0 = byi * TH;

    // ---- load weights: Wc[oc][ic][ky][kx], linear = oc*144 + k ----
    for (int i = tid; i < CTOT * 9 * ZC; i += NTHREADS) {
        int oc = i / (CTOT * 9);
        int k  = i - oc * (CTOT * 9);
        s_w[k][oc] = Wc[i];
    }
    if (tid < ZC) s_b[tid] = bc[tid];

    // ---- load input tile (padded rows): ch 0..7 = X_t, 8..15 = h_{t-1} ----
    float* s_in_flat = &s_in[0][0][0];
    const int tile_elems = CTOT * HALO_H * HALO_WP;
    for (int i = tid; i < tile_elems; i += NTHREADS) {
        int c   = i / (HALO_H * HALO_WP);
        int rem = i - c * (HALO_H * HALO_WP);
        int r   = rem / HALO_WP;
        int col = rem - r * HALO_WP;
        int gy = y0 + r - 1;
        int gxl = x0 + col - 1;
        float v = 0.0f;
        if (col < HALO_W && gy >= 0 && gy < Hh && gxl >= 0 && gxl < Ww) {
            if (c < CINc) {
                v = X[(((size_t)(b * CINc + c) * SEQ + t) * Hh + gy) * Ww + gxl];
            } else if (!FIRST) {
                v = h_prev[((size_t)(b * COUTc + (c - CINc)) * Hh + gy) * Ww + gxl];
            }
        }
        s_in_flat[i] = v;
    }
    __syncthreads();

    // ---- accumulate: 4 pixels x 8 oc-pairs (i0,i1,f0,f1,g0,g1,o0,o1) ----
    // thread's z-channel pairs: i: {2h,2h+1}, f: {4+2h,..}, g: {8+..}, o: {12+..}
    u64 acc[4][8];
    {
        const ulonglong2* bb = reinterpret_cast<const ulonglong2*>(s_b);
        ulonglong2 bi = bb[0 + hf], bf = bb[2 + hf], bg = bb[4 + hf], bo = bb[6 + hf];
#pragma unroll
        for (int p = 0; p < 4; p++) {
            acc[p][0] = bi.x; acc[p][1] = bi.y;
            acc[p][2] = bf.x; acc[p][3] = bf.y;
            acc[p][4] = bg.x; acc[p][5] = bg.y;
            acc[p][6] = bo.x; acc[p][7] = bo.y;
        }
    }

    const int px = tx * 4;  // tile-local x of pixel 0 (16B-aligned in padded row)

#pragma unroll 1
    for (int c = 0; c < CTOT; c++) {
#pragma unroll
        for (int ky = 0; ky < 3; ky++) {
            const float* row = &s_in[c][ty + ky][px];
            float4 vA = *reinterpret_cast<const float4*>(row);      // v0..v3
            float2 vB = *reinterpret_cast<const float2*>(row + 4);  // v4,v5
            u64 pv[6];
            pv[0] = pack2(vA.x); pv[1] = pack2(vA.y);
            pv[2] = pack2(vA.z); pv[3] = pack2(vA.w);
            pv[4] = pack2(vB.x); pv[5] = pack2(vB.y);
            const int tap0 = c * 9 + ky * 3;
#pragma unroll
            for (int kx = 0; kx < 3; kx++) {
                const float* wrow = &s_w[tap0 + kx][0];
                ulonglong2 wi = *reinterpret_cast<const ulonglong2*>(wrow + 4 * hf);
                ulonglong2 wf = *reinterpret_cast<const ulonglong2*>(wrow + 8 + 4 * hf);
                ulonglong2 wg = *reinterpret_cast<const ulonglong2*>(wrow + 16 + 4 * hf);
                ulonglong2 wo = *reinterpret_cast<const ulonglong2*>(wrow + 24 + 4 * hf);
#pragma unroll
                for (int p = 0; p < 4; p++) {
                    u64 a = pv[p + kx];
                    fma2(acc[p][0], a, wi.x, acc[p][0]);
                    fma2(acc[p][1], a, wi.y, acc[p][1]);
                    fma2(acc[p][2], a, wf.x, acc[p][2]);
                    fma2(acc[p][3], a, wf.y, acc[p][3]);
                    fma2(acc[p][4], a, wg.x, acc[p][4]);
                    fma2(acc[p][5], a, wg.y, acc[p][5]);
                    fma2(acc[p][6], a, wo.x, acc[p][6]);
                    fma2(acc[p][7], a, wo.y, acc[p][7]);
                }
            }
        }
    }

    // ---- gates + state update + float4 stores (coalesced) ----
    const int gx = x0 + px;
    const int gy = y0 + ty;
    const size_t pix = (size_t)gy * Ww + gx;

#pragma unroll
    for (int k = 0; k < 4; k++) {             // local cout channel
        const int ch = 4 * hf + k;            // global cout channel
        const int j = k >> 1;                 // pair index within group
        const bool hi = (k & 1) != 0;

        float zi[4], zf[4], zg[4], zo[4];
#pragma unroll
        for (int p = 0; p < 4; p++) {
            zi[p] = hi ? xhi(acc[p][j])     : xlo(acc[p][j]);
            zf[p] = hi ? xhi(acc[p][2 + j]) : xlo(acc[p][2 + j]);
            zg[p] = hi ? xhi(acc[p][4 + j]) : xlo(acc[p][4 + j]);
            zo[p] = hi ? xhi(acc[p][6 + j]) : xlo(acc[p][6 + j]);
        }

        size_t sidx = (size_t)(b * COUTc + ch) * (Hh * Ww) + pix;
        float4 cp = make_float4(0.f, 0.f, 0.f, 0.f);
        if (!FIRST) cp = *reinterpret_cast<const float4*>(&g_c[sidx]);
        float cprev[4] = {cp.x, cp.y, cp.z, cp.w};

        float cn[4], hn[4];
#pragma unroll
        for (int p = 0; p < 4; p++) {
            float ig = sigf(zi[p]);
            float fg = sigf(zf[p]);
            float gg = tanhfast(zg[p]);
            float og = sigf(zo[p]);
            cn[p] = fg * cprev[p] + ig * gg;
            hn[p] = og * tanhfast(cn[p]);
        }

        *reinterpret_cast<float4*>(&g_c[sidx]) = make_float4(cn[0], cn[1], cn[2], cn[3]);
        *reinterpret_cast<float4*>(&h_cur[sidx]) = make_float4(hn[0], hn[1], hn[2], hn[3]);

        size_t oidx = ((size_t)(b * COUTc + ch) * SEQ + t) * (Hh * Ww) + pix;
        *reinterpret_cast<float4*>(&out[oidx]) = make_float4(hn[0], hn[1], hn[2], hn[3]);
    }
}

extern "C" void kernel_launch(void* const* d_in, const int* in_sizes, int n_in,
                              void* d_out, int out_size)
{
    const float* X  = (const float*)d_in[0];
    const float* Wc = (const float*)d_in[1];
    const float* bc = (const float*)d_in[2];
    float* out = (float*)d_out;

    dim3 grid(Ww / TW, Hh / TH, Bn);   // (4, 16, 16) = 1024 blocks
    convlstm_step<true><<<grid, NTHREADS>>>(X, Wc, bc, out, 0);
    for (int t = 1; t < SEQ; t++) {
        convlstm_step<false><<<grid, NTHREADS>>>(X, Wc, bc, out, t);
    }
}

// round 6
// speedup vs baseline: 1.4134x; 1.1074x over previous
#include <cuda_runtime.h>
#include <math.h>

// Problem constants
#define Bn    16
#define CINc  8
#define SEQ   32
#define Hh    128
#define Ww    128
#define COUTc 8
#define ZC    32   // 4*COUT gate channels
#define CTOT  16   // CIN + COUT

// Tiling: 32x8 tile, 256 threads; thread = 4 x-adjacent pixels x 8 z-ch
// (2 cout channels x 4 gates, selected by quarter q)
#define TW 32
#define TH 8
#define NTHREADS 256
#define HALO_W 34
#define HALO_WP 36        // padded so each row is 144B = 16B-aligned
#define HALO_H (TH + 2)   // 10

#define STATE_ELEMS (Bn * COUTc * Hh * Ww)

// Recurrent state. g_h is DOUBLE-BUFFERED: halo reads cross block boundaries,
// so reading (t-1)-state and writing t-state must not alias within one launch.
__device__ float g_h[2][STATE_ELEMS];
__device__ float g_c[STATE_ELEMS];

typedef unsigned long long u64;

__device__ __forceinline__ u64 pack2(float x) {
    u64 r; asm("mov.b64 %0, {%1, %1};" : "=l"(r) : "f"(x)); return r;
}
__device__ __forceinline__ void fma2(u64& d, u64 a, u64 b, u64 c) {
    asm("fma.rn.f32x2 %0, %1, %2, %3;" : "=l"(d) : "l"(a), "l"(b), "l"(c));
}
__device__ __forceinline__ float xlo(u64 v) {
    float lo, hi; asm("mov.b64 {%0, %1}, %2;" : "=f"(lo), "=f"(hi) : "l"(v)); return lo;
}
__device__ __forceinline__ float xhi(u64 v) {
    float lo, hi; asm("mov.b64 {%0, %1}, %2;" : "=f"(lo), "=f"(hi) : "l"(v)); return hi;
}

// Fast gates: verified in R1/R2 that transcendental choice doesn't move
// rel_err at the 1e-6 level.
__device__ __forceinline__ float sigf(float x) {
    return __fdividef(1.0f, 1.0f + __expf(-x));
}
__device__ __forceinline__ float tanhfast(float x) {
    return __fdividef(2.0f, 1.0f + __expf(-2.0f * x)) - 1.0f;
}

template <bool FIRST>
__global__ __launch_bounds__(NTHREADS, 3)
void convlstm_step(const float* __restrict__ X,
                   const float* __restrict__ Wc,
                   const float* __restrict__ bc,
                   float* __restrict__ out,
                   int t)
{
    // weights [tap][oc] (oc contiguous, 128B rows): u64 read = one oc-pair
    __shared__ __align__(16) float s_w[CTOT * 9][ZC];          // 18432 B
    __shared__ __align__(16) float s_in[CTOT][HALO_H][HALO_WP];// 23040 B
    __shared__ __align__(16) float s_b[ZC];

    const float* __restrict__ h_prev = g_h[(t + 1) & 1];
    float* __restrict__ h_cur = g_h[t & 1];

    const int tid = threadIdx.x;
    const int tx = tid & 7;           // 0..7 -> 4-pixel group column
    const int q  = (tid >> 3) & 3;    // 0..3 -> cout-pair quarter (ch 2q,2q+1)
    const int ty = tid >> 5;          // 0..7
    const int bxi = blockIdx.x, byi = blockIdx.y, b = blockIdx.z;
    const int x0 = bxi * TW;
    const int y0 = byi * TH;

    // ---- load weights: Wc[oc][ic][ky][kx], linear = oc*144 + k ----
    for (int i = tid; i < CTOT * 9 * ZC; i += NTHREADS) {
        int oc = i / (CTOT * 9);
        int k  = i - oc * (CTOT * 9);
        s_w[k][oc] = Wc[i];
    }
    if (tid < ZC) s_b[tid] = bc[tid];

    // ---- load input tile (padded rows): ch 0..7 = X_t, 8..15 = h_{t-1} ----
    float* s_in_flat = &s_in[0][0][0];
    const int tile_elems = CTOT * HALO_H * HALO_WP;
    for (int i = tid; i < tile_elems; i += NTHREADS) {
        int c   = i / (HALO_H * HALO_WP);
        int rem = i - c * (HALO_H * HALO_WP);
        int r   = rem / HALO_WP;
        int col = rem - r * HALO_WP;
        int gy = y0 + r - 1;
        int gxl = x0 + col - 1;
        float v = 0.0f;
        if (col < HALO_W && gy >= 0 && gy < Hh && gxl >= 0 && gxl < Ww) {
            if (c < CINc) {
                v = X[(((size_t)(b * CINc + c) * SEQ + t) * Hh + gy) * Ww + gxl];
            } else if (!FIRST) {
                v = h_prev[((size_t)(b * COUTc + (c - CINc)) * Hh + gy) * Ww + gxl];
            }
        }
        s_in_flat[i] = v;
    }
    __syncthreads();

    // ---- accumulate: 4 pixels x 4 z-pairs {i,f,g,o} for cout pair (2q,2q+1) ----
    u64 acc[4][4];   // [pixel][gate] ; 32 registers total
    {
        const u64* b64 = reinterpret_cast<const u64*>(s_b);
        u64 bi = b64[q], bf = b64[4 + q], bg = b64[8 + q], bo = b64[12 + q];
#pragma unroll
        for (int p = 0; p < 4; p++) {
            acc[p][0] = bi; acc[p][1] = bf; acc[p][2] = bg; acc[p][3] = bo;
        }
    }

    const int px = tx * 4;  // tile-local x of pixel 0 (16B-aligned in padded row)

#pragma unroll 1
    for (int c = 0; c < CTOT; c++) {
#pragma unroll
        for (int ky = 0; ky < 3; ky++) {
            const float* row = &s_in[c][ty + ky][px];
            float4 vA = *reinterpret_cast<const float4*>(row);      // v0..v3
            float2 vB = *reinterpret_cast<const float2*>(row + 4);  // v4,v5
            u64 pv[6];
            pv[0] = pack2(vA.x); pv[1] = pack2(vA.y);
            pv[2] = pack2(vA.z); pv[3] = pack2(vA.w);
            pv[4] = pack2(vB.x); pv[5] = pack2(vB.y);
            const int tap0 = c * 9 + ky * 3;
#pragma unroll
            for (int kx = 0; kx < 3; kx++) {
                const u64* w64 = reinterpret_cast<const u64*>(&s_w[tap0 + kx][0]);
                u64 wi = w64[q];
                u64 wf = w64[4 + q];
                u64 wg = w64[8 + q];
                u64 wo = w64[12 + q];
#pragma unroll
                for (int p = 0; p < 4; p++) {
                    u64 a = pv[p + kx];
                    fma2(acc[p][0], a, wi, acc[p][0]);
                    fma2(acc[p][1], a, wf, acc[p][1]);
                    fma2(acc[p][2], a, wg, acc[p][2]);
                    fma2(acc[p][3], a, wo, acc[p][3]);
                }
            }
        }
    }

    // ---- gates + state update + float4 stores (coalesced) ----
    const int gx = x0 + px;
    const int gy = y0 + ty;
    const size_t pix = (size_t)gy * Ww + gx;

#pragma unroll
    for (int k = 0; k < 2; k++) {             // local cout channel within pair
        const int ch = 2 * q + k;             // global cout channel
        const bool hi = (k != 0);

        float zi[4], zf[4], zg[4], zo[4];
#pragma unroll
        for (int p = 0; p < 4; p++) {
            zi[p] = hi ? xhi(acc[p][0]) : xlo(acc[p][0]);
            zf[p] = hi ? xhi(acc[p][1]) : xlo(acc[p][1]);
            zg[p] = hi ? xhi(acc[p][2]) : xlo(acc[p][2]);
            zo[p] = hi ? xhi(acc[p][3]) : xlo(acc[p][3]);
        }

        size_t sidx = (size_t)(b * COUTc + ch) * (Hh * Ww) + pix;
        float4 cp = make_float4(0.f, 0.f, 0.f, 0.f);
        if (!FIRST) cp = *reinterpret_cast<const float4*>(&g_c[sidx]);
        float cprev[4] = {cp.x, cp.y, cp.z, cp.w};

        float cn[4], hn[4];
#pragma unroll
        for (int p = 0; p < 4; p++) {
            float ig = sigf(zi[p]);
            float fg = sigf(zf[p]);
            float gg = tanhfast(zg[p]);
            float og = sigf(zo[p]);
            cn[p] = fg * cprev[p] + ig * gg;
            hn[p] = og * tanhfast(cn[p]);
        }

        *reinterpret_cast<float4*>(&g_c[sidx]) = make_float4(cn[0], cn[1], cn[2], cn[3]);
        *reinterpret_cast<float4*>(&h_cur[sidx]) = make_float4(hn[0], hn[1], hn[2], hn[3]);

        size_t oidx = ((size_t)(b * COUTc + ch) * SEQ + t) * (Hh * Ww) + pix;
        *reinterpret_cast<float4*>(&out[oidx]) = make_float4(hn[0], hn[1], hn[2], hn[3]);
    }
}

extern "C" void kernel_launch(void* const* d_in, const int* in_sizes, int n_in,
                              void* d_out, int out_size)
{
    const float* X  = (const float*)d_in[0];
    const float* Wc = (const float*)d_in[1];
    const float* bc = (const float*)d_in[2];
    float* out = (float*)d_out;

    dim3 grid(Ww / TW, Hh / TH, Bn);   // (4, 16, 16) = 1024 blocks
    convlstm_step<true><<<grid, NTHREADS>>>(X, Wc, bc, out, 0);
    for (int t = 1; t < SEQ; t++) {
        convlstm_step<false><<<grid, NTHREADS>>>(X, Wc, bc, out, t);
    }
}

// round 8
// speedup vs baseline: 1.5802x; 1.1180x over previous
#include <cuda_runtime.h>
#include <math.h>

// Problem constants
#define Bn    16
#define CINc  8
#define SEQ   32
#define Hh    128
#define Ww    128
#define COUTc 8
#define ZC    32   // 4*COUT gate channels
#define CTOT  16   // CIN + COUT

// Tiling: 32x8 tile, 256 threads; thread = 4 x-adjacent pixels x 8 z-ch
// (2 cout channels x 4 gates, selected by quarter q)
#define TW 32
#define TH 8
#define NTHREADS 256
#define HALO_W 34
#define HALO_WP 36        // padded so each row is 144B = 16B-aligned
#define HALO_H (TH + 2)   // 10

#define STATE_ELEMS (Bn * COUTc * Hh * Ww)

// Recurrent state. g_h is DOUBLE-BUFFERED: halo reads cross block boundaries,
// so reading (t-1)-state and writing t-state must not alias within one launch.
__device__ float g_h[2][STATE_ELEMS];
__device__ float g_c[STATE_ELEMS];

typedef unsigned long long u64;

__device__ __forceinline__ u64 pack2(float x) {
    u64 r; asm("mov.b64 %0, {%1, %1};" : "=l"(r) : "f"(x)); return r;
}
__device__ __forceinline__ void fma2(u64& d, u64 a, u64 b, u64 c) {
    asm("fma.rn.f32x2 %0, %1, %2, %3;" : "=l"(d) : "l"(a), "l"(b), "l"(c));
}
__device__ __forceinline__ float xlo(u64 v) {
    float lo, hi; asm("mov.b64 {%0, %1}, %2;" : "=f"(lo), "=f"(hi) : "l"(v)); return lo;
}
__device__ __forceinline__ float xhi(u64 v) {
    float lo, hi; asm("mov.b64 {%0, %1}, %2;" : "=f"(lo), "=f"(hi) : "l"(v)); return hi;
}

// Fast gates: verified in R1/R2 that transcendental choice doesn't move
// rel_err at the 1e-6 level.
__device__ __forceinline__ float sigf(float x) {
    return __fdividef(1.0f, 1.0f + __expf(-x));
}
__device__ __forceinline__ float tanhfast(float x) {
    return __fdividef(2.0f, 1.0f + __expf(-2.0f * x)) - 1.0f;
}

template <bool FIRST>
__global__ __launch_bounds__(NTHREADS, 4)
void convlstm_step(const float* __restrict__ X,
                   const float* __restrict__ Wc,
                   const float* __restrict__ bc,
                   float* __restrict__ out,
                   int t)
{
    // Weights reordered per quarter q: s_w[tap][q][8] = {i0,i1,f0,f1,g0,g1,o0,o1}
    // for cout pair (2q, 2q+1). One thread's weights per tap = 2 x LDS.128.
    __shared__ __align__(16) float s_w[CTOT * 9][4][8];        // 18432 B
    __shared__ __align__(16) float s_in[CTOT][HALO_H][HALO_WP];// 23040 B
    __shared__ __align__(16) float s_b[ZC];                    // reordered likewise

    const float* __restrict__ h_prev = g_h[(t + 1) & 1];
    float* __restrict__ h_cur = g_h[t & 1];

    const int tid = threadIdx.x;
    const int tx = tid & 7;           // 0..7 -> 4-pixel group column
    const int q  = (tid >> 3) & 3;    // 0..3 -> cout-pair quarter (ch 2q,2q+1)
    const int ty = tid >> 5;          // 0..7
    const int bxi = blockIdx.x, byi = blockIdx.y, b = blockIdx.z;
    const int x0 = bxi * TW;
    const int y0 = byi * TH;

    // ---- load weights into reordered layout ----
    // dest index r in [0,32): qd = r>>3, j = r&7, gate g = j>>1, half hh = j&1
    // source oc = g*8 + 2*qd + hh ; Wc linear = oc*144 + tap
    for (int i = tid; i < CTOT * 9 * ZC; i += NTHREADS) {
        int tap = i >> 5;
        int r   = i & 31;
        int qd  = r >> 3;
        int j   = r & 7;
        int g   = j >> 1;
        int hh  = j & 1;
        int oc  = g * 8 + 2 * qd + hh;
        s_w[tap][qd][j] = Wc[oc * (CTOT * 9) + tap];
    }
    if (tid < ZC) {
        int qd = tid >> 3, j = tid & 7, g = j >> 1, hh = j & 1;
        s_b[tid] = bc[g * 8 + 2 * qd + hh];
    }

    // ---- load input tile (padded rows): ch 0..7 = X_t, 8..15 = h_{t-1} ----
    float* s_in_flat = &s_in[0][0][0];
    const int tile_elems = CTOT * HALO_H * HALO_WP;
    for (int i = tid; i < tile_elems; i += NTHREADS) {
        int c   = i / (HALO_H * HALO_WP);
        int rem = i - c * (HALO_H * HALO_WP);
        int r   = rem / HALO_WP;
        int col = rem - r * HALO_WP;
        int gy = y0 + r - 1;
        int gxl = x0 + col - 1;
        float v = 0.0f;
        if (col < HALO_W && gy >= 0 && gy < Hh && gxl >= 0 && gxl < Ww) {
            if (c < CINc) {
                v = X[(((size_t)(b * CINc + c) * SEQ + t) * Hh + gy) * Ww + gxl];
            } else if (!FIRST) {
                v = h_prev[((size_t)(b * COUTc + (c - CINc)) * Hh + gy) * Ww + gxl];
            }
        }
        s_in_flat[i] = v;
    }
    __syncthreads();

    // ---- accumulate: 4 pixels x 4 z-pairs {i,f,g,o} for cout pair (2q,2q+1) ----
    u64 acc[4][4];   // [pixel][gate] ; 32 registers
    {
        const ulonglong2* bb = reinterpret_cast<const ulonglong2*>(&s_b[q * 8]);
        ulonglong2 bA = bb[0];   // {bi, bf}
        ulonglong2 bB = bb[1];   // {bg, bo}
#pragma unroll
        for (int p = 0; p < 4; p++) {
            acc[p][0] = bA.x; acc[p][1] = bA.y; acc[p][2] = bB.x; acc[p][3] = bB.y;
        }
    }

    const int px = tx * 4;  // tile-local x of pixel 0 (16B-aligned in padded row)

#pragma unroll 1
    for (int c = 0; c < CTOT; c++) {
#pragma unroll
        for (int ky = 0; ky < 3; ky++) {
            const float* row = &s_in[c][ty + ky][px];
            float4 vA = *reinterpret_cast<const float4*>(row);      // v0..v3
            float2 vB = *reinterpret_cast<const float2*>(row + 4);  // v4,v5
            u64 pv[6];
            pv[0] = pack2(vA.x); pv[1] = pack2(vA.y);
            pv[2] = pack2(vA.z); pv[3] = pack2(vA.w);
            pv[4] = pack2(vB.x); pv[5] = pack2(vB.y);
            const ulonglong2* wbase =
                reinterpret_cast<const ulonglong2*>(&s_w[c * 9 + ky * 3][q][0]);
#pragma unroll
            for (int kx = 0; kx < 3; kx++) {
                // tap stride = 32 floats = 128 B = 8 ulonglong2 (NOT 2!)
                ulonglong2 wA = wbase[kx * 8];      // {wi, wf}
                ulonglong2 wB = wbase[kx * 8 + 1];  // {wg, wo}
#pragma unroll
                for (int p = 0; p < 4; p++) {
                    u64 a = pv[p + kx];
                    fma2(acc[p][0], a, wA.x, acc[p][0]);
                    fma2(acc[p][1], a, wA.y, acc[p][1]);
                    fma2(acc[p][2], a, wB.x, acc[p][2]);
                    fma2(acc[p][3], a, wB.y, acc[p][3]);
                }
            }
        }
    }

    // ---- gates + state update + float4 stores (coalesced) ----
    const int gx = x0 + px;
    const int gy = y0 + ty;
    const size_t pix = (size_t)gy * Ww + gx;

#pragma unroll
    for (int k = 0; k < 2; k++) {             // local cout channel within pair
        const int ch = 2 * q + k;             // global cout channel
        const bool hi = (k != 0);

        float zi[4], zf[4], zg[4], zo[4];
#pragma unroll
        for (int p = 0; p < 4; p++) {
            zi[p] = hi ? xhi(acc[p][0]) : xlo(acc[p][0]);
            zf[p] = hi ? xhi(acc[p][1]) : xlo(acc[p][1]);
            zg[p] = hi ? xhi(acc[p][2]) : xlo(acc[p][2]);
            zo[p] = hi ? xhi(acc[p][3]) : xlo(acc[p][3]);
        }

        size_t sidx = (size_t)(b * COUTc + ch) * (Hh * Ww) + pix;
        float4 cp = make_float4(0.f, 0.f, 0.f, 0.f);
        if (!FIRST) cp = *reinterpret_cast<const float4*>(&g_c[sidx]);
        float cprev[4] = {cp.x, cp.y, cp.z, cp.w};

        float cn[4], hn[4];
#pragma unroll
        for (int p = 0; p < 4; p++) {
            float ig = sigf(zi[p]);
            float fg = sigf(zf[p]);
            float gg = tanhfast(zg[p]);
            float og = sigf(zo[p]);
            cn[p] = fg * cprev[p] + ig * gg;
            hn[p] = og * tanhfast(cn[p]);
        }

        *reinterpret_cast<float4*>(&g_c[sidx]) = make_float4(cn[0], cn[1], cn[2], cn[3]);
        *reinterpret_cast<float4*>(&h_cur[sidx]) = make_float4(hn[0], hn[1], hn[2], hn[3]);

        size_t oidx = ((size_t)(b * COUTc + ch) * SEQ + t) * (Hh * Ww) + pix;
        *reinterpret_cast<float4*>(&out[oidx]) = make_float4(hn[0], hn[1], hn[2], hn[3]);
    }
}

extern "C" void kernel_launch(void* const* d_in, const int* in_sizes, int n_in,
                              void* d_out, int out_size)
{
    const float* X  = (const float*)d_in[0];
    const float* Wc = (const float*)d_in[1];
    const float* bc = (const float*)d_in[2];
    float* out = (float*)d_out;

    dim3 grid(Ww / TW, Hh / TH, Bn);   // (4, 16, 16) = 1024 blocks
    convlstm_step<true><<<grid, NTHREADS>>>(X, Wc, bc, out, 0);
    for (int t = 1; t < SEQ; t++) {
        convlstm_step<false><<<grid, NTHREADS>>>(X, Wc, bc, out, t);
    }
}

// round 10
// speedup vs baseline: 1.6564x; 1.0482x over previous
#include <cuda_runtime.h>
#include <cuda_fp16.h>
#include <math.h>
#include <stdint.h>

// Problem constants
#define Bn    16
#define CINc  8
#define SEQ   32
#define Hh    128
#define Ww    128
#define COUTc 8
#define ZC    32      // 4*COUT gate channels (N)
#define CTOT  16      // CIN + COUT
#define KTOT  144     // 9 taps * 16 channels (K); k = tap*16 + c

#define NT    128     // 4 warps; warp w owns pixel rows [w*32, w*32+32)
#define XP    132     // padded strip row length (floats); left pad 1
#define STRIP_FLOATS (3 * CTOT * XP)   // 6336

#define BROW  152     // padded B row length in halves (76 u32: conflict-free)

#define STATE_ELEMS (Bn * COUTc * Hh * Ww)
__device__ float g_h[2][STATE_ELEMS];   // ping-pong h (cross-block halo safety)
__device__ float g_c[STATE_ELEMS];
__device__ __align__(16) __half g_Bh[ZC * BROW];  // f16 hi split, [n][k] padded
__device__ __align__(16) __half g_Bl[ZC * BROW];  // f16 lo split

__device__ __forceinline__ float sigf(float x) {
    return __fdividef(1.0f, 1.0f + __expf(-x));
}
__device__ __forceinline__ float tanhfast(float x) {
    return __fdividef(2.0f, 1.0f + __expf(-2.0f * x)) - 1.0f;
}

// pack two f32 into f16x2 (lo = v0) and compute the f16x2 residual pack
__device__ __forceinline__ void pack_split(float v0, float v1,
                                           uint32_t& hi, uint32_t& lo) {
    asm("cvt.rn.f16x2.f32 %0, %1, %2;" : "=r"(hi) : "f"(v1), "f"(v0));
    float h0, h1;
    asm("{ .reg .b16 l,h; mov.b32 {l,h}, %2; cvt.f32.f16 %0, l; cvt.f32.f16 %1, h; }"
        : "=f"(h0), "=f"(h1) : "r"(hi));
    float r0 = v0 - h0, r1 = v1 - h1;
    asm("cvt.rn.f16x2.f32 %0, %1, %2;" : "=r"(lo) : "f"(r1), "f"(r0));
}

__device__ __forceinline__ void mma16816(float* d, const uint32_t* a,
                                         uint32_t b0, uint32_t b1) {
    asm volatile(
        "mma.sync.aligned.m16n8k16.row.col.f32.f16.f16.f32 "
        "{%0,%1,%2,%3}, {%4,%5,%6,%7}, {%8,%9}, {%0,%1,%2,%3};"
        : "+f"(d[0]), "+f"(d[1]), "+f"(d[2]), "+f"(d[3])
        : "r"(a[0]), "r"(a[1]), "r"(a[2]), "r"(a[3]), "r"(b0), "r"(b1));
}

// ---- prep: f16 hi/lo splits of B[n][k], k = tap*16 + c, padded rows ----
// Wc linear = n*144 + c*9 + tap
__global__ void prep_B(const float* __restrict__ Wc) {
    for (int i = threadIdx.x; i < ZC * KTOT; i += blockDim.x) {
        int n = i / KTOT;
        int k = i - n * KTOT;
        int c = k & 15;
        int tap = k >> 4;
        float w = Wc[n * KTOT + c * 9 + tap];
        __half wh = __float2half_rn(w);
        __half wl = __float2half_rn(w - __half2float(wh));
        g_Bh[n * BROW + k] = wh;
        g_Bl[n * BROW + k] = wl;
    }
}

// ---- main: one CTA = one image row (M=128 px) x N=32 x K=144 ----
template <bool FIRST>
__global__ __launch_bounds__(NT)
void convlstm_hmma(const float* __restrict__ X,
                   const float* __restrict__ bc,
                   float* __restrict__ out,
                   int t)
{
    __shared__ __align__(16) float  s_x[STRIP_FLOATS];       // 25344 B
    __shared__ __align__(16) __half s_bh[ZC * BROW];         // 9728 B
    __shared__ __align__(16) __half s_bl[ZC * BROW];         // 9728 B
    __shared__ float s_bias[ZC];

    const int tid  = threadIdx.x;
    const int w    = tid >> 5;
    const int lane = tid & 31;
    const int g    = lane >> 2;   // groupID (fragment row within tile)
    const int tg   = lane & 3;    // thread-in-group (fragment col pair)
    const int y = blockIdx.x, b = blockIdx.y;

    const float* __restrict__ h_prev = g_h[(t + 1) & 1];
    float* __restrict__ h_cur = g_h[t & 1];

    // zero strip
    {
        float4 z4 = make_float4(0.f, 0.f, 0.f, 0.f);
        float4* xs4 = reinterpret_cast<float4*>(s_x);
        for (int i = tid; i < STRIP_FLOATS / 4; i += NT) xs4[i] = z4;
    }
    // copy B splits
    {
        const uint4* sh = reinterpret_cast<const uint4*>(g_Bh);
        const uint4* sl = reinterpret_cast<const uint4*>(g_Bl);
        uint4* dh = reinterpret_cast<uint4*>(s_bh);
        uint4* dl = reinterpret_cast<uint4*>(s_bl);
        for (int i = tid; i < (ZC * BROW * 2) / 16; i += NT) { dh[i] = sh[i]; dl[i] = sl[i]; }
    }
    if (tid < ZC) s_bias[tid] = bc[tid];
    __syncthreads();

    // fill strip: plane p = r*16 + c (r = y-1..y+1), column xi+1
    for (int i = tid; i < 48 * 128; i += NT) {
        int p  = i >> 7;
        int xi = i & 127;
        int r  = p >> 4;
        int c  = p & 15;
        int gy = y + r - 1;
        if (gy >= 0 && gy < Hh) {
            float v;
            if (c < CINc) {
                v = X[(((size_t)(b * CINc + c) * SEQ + t) * Hh + gy) * Ww + xi];
            } else if (!FIRST) {
                v = h_prev[((size_t)(b * COUTc + (c - CINc)) * Hh + gy) * Ww + xi];
            } else {
                continue;
            }
            s_x[p * XP + xi + 1] = v;
        }
    }
    __syncthreads();

    // accumulators: [m-tile][n-tile][frag reg]
    float d[2][4][4];
#pragma unroll
    for (int mt = 0; mt < 2; mt++)
#pragma unroll
        for (int nt = 0; nt < 4; nt++)
#pragma unroll
            for (int r = 0; r < 4; r++) d[mt][nt][r] = 0.0f;

    const uint32_t* bh32 = reinterpret_cast<const uint32_t*>(s_bh);
    const uint32_t* bl32 = reinterpret_cast<const uint32_t*>(s_bl);

#pragma unroll 1
    for (int tap = 0; tap < 9; tap++) {
        const int ky = tap / 3;
        const int kx = tap - ky * 3;
        // A gather base: plane = ky*16 + tg*2, x = w*32 + g + kx
        const float* base = s_x + (ky * 16 + tg * 2) * XP + (w * 32 + g + kx);

        uint32_t ah[2][4], al[2][4];
#pragma unroll
        for (int mt = 0; mt < 2; mt++) {
            const float* bm = base + mt * 16;
            // a0: row g,    cols c0,c0+1 ; a1: row g+8 ; a2/a3: cols +8
            pack_split(bm[0],           bm[XP],           ah[mt][0], al[mt][0]);
            pack_split(bm[8],           bm[XP + 8],       ah[mt][1], al[mt][1]);
            pack_split(bm[8 * XP],      bm[9 * XP],       ah[mt][2], al[mt][2]);
            pack_split(bm[8 * XP + 8],  bm[9 * XP + 8],   ah[mt][3], al[mt][3]);
        }

#pragma unroll
        for (int nt = 0; nt < 4; nt++) {
            // n = nt*8 + g ; u32 index = n*(BROW/2) + tap*8 + tg ; b1 at +4
            const int bi = (nt * 8 + g) * (BROW / 2) + tap * 8 + tg;
            uint32_t bh0 = bh32[bi],     bh1 = bh32[bi + 4];
            uint32_t bl0 = bl32[bi],     bl1 = bl32[bi + 4];
#pragma unroll
            for (int mt = 0; mt < 2; mt++) {
                mma16816(d[mt][nt], ah[mt], bh0, bh1);  // Ah*Bh
                mma16816(d[mt][nt], al[mt], bh0, bh1);  // Al*Bh
                mma16816(d[mt][nt], ah[mt], bl0, bl1);  // Ah*Bl
            }
        }
    }

    // ---- epilogue: gates + state + output ----
    // D frag: c0:(row g, col tg*2) c1:(row g, col tg*2+1) c2:(row g+8, ...) c3
    // n-tile nt = gate (0=i,1=f,2=g,3=o); cout channel = tg*2 + e
#pragma unroll
    for (int mt = 0; mt < 2; mt++) {
#pragma unroll
        for (int rs = 0; rs < 2; rs++) {
            const int x = w * 32 + mt * 16 + rs * 8 + g;
#pragma unroll
            for (int e = 0; e < 2; e++) {
                const int ch = tg * 2 + e;
                const int ri = rs * 2 + e;
                float zi = d[mt][0][ri] + s_bias[ch];
                float zf = d[mt][1][ri] + s_bias[8 + ch];
                float zg = d[mt][2][ri] + s_bias[16 + ch];
                float zo = d[mt][3][ri] + s_bias[24 + ch];

                float ig = sigf(zi);
                float fg = sigf(zf);
                float gg = tanhfast(zg);
                float og = sigf(zo);

                size_t sidx = ((size_t)(b * COUTc + ch) * Hh + y) * Ww + x;
                float cp = FIRST ? 0.0f : g_c[sidx];
                float cn = fg * cp + ig * gg;
                float hn = og * tanhfast(cn);
                g_c[sidx] = cn;
                h_cur[sidx] = hn;
                out[((size_t)(b * COUTc + ch) * SEQ + t) * (Hh * Ww)
                    + (size_t)y * Ww + x] = hn;
            }
        }
    }
}

extern "C" void kernel_launch(void* const* d_in, const int* in_sizes, int n_in,
                              void* d_out, int out_size)
{
    const float* X  = (const float*)d_in[0];
    const float* Wc = (const float*)d_in[1];
    const float* bc = (const float*)d_in[2];
    float* out = (float*)d_out;

    prep_B<<<1, 256>>>(Wc);

    dim3 grid(Hh, Bn);   // (y, b): 2048 CTAs x 128 threads
    convlstm_hmma<true><<<grid, NT>>>(X, bc, out, 0);
    for (int t = 1; t < SEQ; t++) {
        convlstm_hmma<false><<<grid, NT>>>(X, bc, out, t);
    }
}

// round 11
// speedup vs baseline: 2.4443x; 1.4757x over previous
#include <cuda_runtime.h>
#include <cuda_fp16.h>
#include <math.h>
#include <stdint.h>

// Problem constants
#define Bn    16
#define CINc  8
#define SEQ   32
#define Hh    128
#define Ww    128
#define COUTc 8
#define ZC    32      // 4*COUT gate channels (N)
#define CTOT  16      // CIN + COUT
#define KTOT  144     // 9 taps * 16 channels (K); k = tap*16 + c

#define NT    256     // 8 warps; warp w: output row yl=w>>2, x0=(w&3)*32
#define XP    132     // padded strip row length (floats); left pad 1
#define NPLANES 64    // 4 y-rows x 16 channels
#define STRIP_FLOATS (NPLANES * XP)    // 8448

#define BROW  152     // padded B row length in halves (76 u32: conflict-free)

// dynamic smem layout (bytes)
#define S_X    0
#define S_BH   33792                  // STRIP_FLOATS*4
#define S_BL   (S_BH + ZC * BROW * 2) // +9728 = 43520
#define S_BIAS (S_BL + ZC * BROW * 2) // 53248
#define S_TOTAL (S_BIAS + 128)        // 53376

#define STATE_ELEMS (Bn * COUTc * Hh * Ww)
__device__ float g_h[2][STATE_ELEMS];   // ping-pong h (cross-block halo safety)
__device__ float g_c[STATE_ELEMS];
__device__ __align__(16) __half g_Bh[ZC * BROW];  // f16 hi split, [n][k] padded
__device__ __align__(16) __half g_Bl[ZC * BROW];  // f16 lo split

__device__ __forceinline__ float sigf(float x) {
    return __fdividef(1.0f, 1.0f + __expf(-x));
}
__device__ __forceinline__ float tanhfast(float x) {
    return __fdividef(2.0f, 1.0f + __expf(-2.0f * x)) - 1.0f;
}

// pack two f32 into f16x2 (lo = v0) and compute the f16x2 residual pack
__device__ __forceinline__ void pack_split(float v0, float v1,
                                           uint32_t& hi, uint32_t& lo) {
    asm("cvt.rn.f16x2.f32 %0, %1, %2;" : "=r"(hi) : "f"(v1), "f"(v0));
    float h0, h1;
    asm("{ .reg .b16 l,h; mov.b32 {l,h}, %2; cvt.f32.f16 %0, l; cvt.f32.f16 %1, h; }"
        : "=f"(h0), "=f"(h1) : "r"(hi));
    float r0 = v0 - h0, r1 = v1 - h1;
    asm("cvt.rn.f16x2.f32 %0, %1, %2;" : "=r"(lo) : "f"(r1), "f"(r0));
}

__device__ __forceinline__ void mma16816(float* d, const uint32_t* a,
                                         uint32_t b0, uint32_t b1) {
    asm volatile(
        "mma.sync.aligned.m16n8k16.row.col.f32.f16.f16.f32 "
        "{%0,%1,%2,%3}, {%4,%5,%6,%7}, {%8,%9}, {%0,%1,%2,%3};"
        : "+f"(d[0]), "+f"(d[1]), "+f"(d[2]), "+f"(d[3])
        : "r"(a[0]), "r"(a[1]), "r"(a[2]), "r"(a[3]), "r"(b0), "r"(b1));
}

// ---- prep: f16 hi/lo splits of B[n][k], k = tap*16 + c, padded rows ----
// Wc linear = n*144 + c*9 + tap
__global__ void prep_B(const float* __restrict__ Wc) {
    for (int i = threadIdx.x; i < ZC * KTOT; i += blockDim.x) {
        int n = i / KTOT;
        int k = i - n * KTOT;
        int c = k & 15;
        int tap = k >> 4;
        float w = Wc[n * KTOT + c * 9 + tap];
        __half wh = __float2half_rn(w);
        __half wl = __float2half_rn(w - __half2float(wh));
        g_Bh[n * BROW + k] = wh;
        g_Bl[n * BROW + k] = wl;
    }
}

// ---- main: one CTA = TWO image rows (M=256 px) x N=32 x K=144 ----
template <bool FIRST>
__global__ __launch_bounds__(NT, 4)
void convlstm_hmma(const float* __restrict__ X,
                   const float* __restrict__ bc,
                   float* __restrict__ out,
                   int t)
{
    extern __shared__ __align__(16) char smem[];
    float*  s_x    = reinterpret_cast<float*>(smem + S_X);
    __half* s_bh   = reinterpret_cast<__half*>(smem + S_BH);
    __half* s_bl   = reinterpret_cast<__half*>(smem + S_BL);
    float*  s_bias = reinterpret_cast<float*>(smem + S_BIAS);

    const int tid  = threadIdx.x;
    const int w    = tid >> 5;
    const int lane = tid & 31;
    const int g    = lane >> 2;   // fragment row within tile
    const int tg   = lane & 3;    // fragment k-col pair
    const int yl   = w >> 2;      // 0/1: which output row of the pair
    const int x0   = (w & 3) * 32;
    const int y0 = blockIdx.x * 2, b = blockIdx.y;

    const float* __restrict__ h_prev = g_h[(t + 1) & 1];
    float* __restrict__ h_cur = g_h[t & 1];

    // zero strip
    {
        float4 z4 = make_float4(0.f, 0.f, 0.f, 0.f);
        float4* xs4 = reinterpret_cast<float4*>(s_x);
        for (int i = tid; i < STRIP_FLOATS / 4; i += NT) xs4[i] = z4;
    }
    // copy B splits
    {
        const uint4* sh = reinterpret_cast<const uint4*>(g_Bh);
        const uint4* sl = reinterpret_cast<const uint4*>(g_Bl);
        uint4* dh = reinterpret_cast<uint4*>(s_bh);
        uint4* dl = reinterpret_cast<uint4*>(s_bl);
        for (int i = tid; i < (ZC * BROW * 2) / 16; i += NT) { dh[i] = sh[i]; dl[i] = sl[i]; }
    }
    if (tid < ZC) s_bias[tid] = bc[tid];
    __syncthreads();

    // fill strip: plane p = r*16 + c (r = 0..3 -> gy = y0 + r - 1), column xi+1
    for (int i = tid; i < NPLANES * 128; i += NT) {
        int p  = i >> 7;
        int xi = i & 127;
        int r  = p >> 4;
        int c  = p & 15;
        int gy = y0 + r - 1;
        if (gy >= 0 && gy < Hh) {
            float v;
            if (c < CINc) {
                v = X[(((size_t)(b * CINc + c) * SEQ + t) * Hh + gy) * Ww + xi];
            } else if (!FIRST) {
                v = h_prev[((size_t)(b * COUTc + (c - CINc)) * Hh + gy) * Ww + xi];
            } else {
                continue;
            }
            s_x[p * XP + xi + 1] = v;
        }
    }
    __syncthreads();

    // accumulators: [m-tile][n-tile][frag reg]
    float d[2][4][4];
#pragma unroll
    for (int mt = 0; mt < 2; mt++)
#pragma unroll
        for (int nt = 0; nt < 4; nt++)
#pragma unroll
            for (int r = 0; r < 4; r++) d[mt][nt][r] = 0.0f;

    const uint32_t* bh32 = reinterpret_cast<const uint32_t*>(s_bh);
    const uint32_t* bl32 = reinterpret_cast<const uint32_t*>(s_bl);

#pragma unroll 1
    for (int tap = 0; tap < 9; tap++) {
        const int ky = tap / 3;
        const int kx = tap - ky * 3;
        // A gather base: plane = (yl+ky)*16 + tg*2, x = x0 + g + kx
        const float* base = s_x + ((yl + ky) * 16 + tg * 2) * XP + (x0 + g + kx);

        uint32_t ah[2][4], al[2][4];
#pragma unroll
        for (int mt = 0; mt < 2; mt++) {
            const float* bm = base + mt * 16;
            pack_split(bm[0],           bm[XP],           ah[mt][0], al[mt][0]);
            pack_split(bm[8],           bm[XP + 8],       ah[mt][1], al[mt][1]);
            pack_split(bm[8 * XP],      bm[9 * XP],       ah[mt][2], al[mt][2]);
            pack_split(bm[8 * XP + 8],  bm[9 * XP + 8],   ah[mt][3], al[mt][3]);
        }

#pragma unroll
        for (int nt = 0; nt < 4; nt++) {
            const int bi = (nt * 8 + g) * (BROW / 2) + tap * 8 + tg;
            uint32_t bh0 = bh32[bi], bh1 = bh32[bi + 4];
            uint32_t bl0 = bl32[bi], bl1 = bl32[bi + 4];
#pragma unroll
            for (int mt = 0; mt < 2; mt++) {
                mma16816(d[mt][nt], ah[mt], bh0, bh1);  // Ah*Bh
                mma16816(d[mt][nt], al[mt], bh0, bh1);  // Al*Bh
                mma16816(d[mt][nt], ah[mt], bl0, bl1);  // Ah*Bl
            }
        }
    }

    // ---- epilogue: gates + state + output ----
    const int y = y0 + yl;
#pragma unroll
    for (int mt = 0; mt < 2; mt++) {
#pragma unroll
        for (int rs = 0; rs < 2; rs++) {
            const int x = x0 + mt * 16 + rs * 8 + g;
#pragma unroll
            for (int e = 0; e < 2; e++) {
                const int ch = tg * 2 + e;
                const int ri = rs * 2 + e;
                float zi = d[mt][0][ri] + s_bias[ch];
                float zf = d[mt][1][ri] + s_bias[8 + ch];
                float zg = d[mt][2][ri] + s_bias[16 + ch];
                float zo = d[mt][3][ri] + s_bias[24 + ch];

                float ig = sigf(zi);
                float fg = sigf(zf);
                float gg = tanhfast(zg);
                float og = sigf(zo);

                size_t sidx = ((size_t)(b * COUTc + ch) * Hh + y) * Ww + x;
                float cp = FIRST ? 0.0f : g_c[sidx];
                float cn = fg * cp + ig * gg;
                float hn = og * tanhfast(cn);
                g_c[sidx] = cn;
                h_cur[sidx] = hn;
                out[((size_t)(b * COUTc + ch) * SEQ + t) * (Hh * Ww)
                    + (size_t)y * Ww + x] = hn;
            }
        }
    }
}

extern "C" void kernel_launch(void* const* d_in, const int* in_sizes, int n_in,
                              void* d_out, int out_size)
{
    const float* X  = (const float*)d_in[0];
    const float* Wc = (const float*)d_in[1];
    const float* bc = (const float*)d_in[2];
    float* out = (float*)d_out;

    cudaFuncSetAttribute(convlstm_hmma<true>,
                         cudaFuncAttributeMaxDynamicSharedMemorySize, S_TOTAL);
    cudaFuncSetAttribute(convlstm_hmma<false>,
                         cudaFuncAttributeMaxDynamicSharedMemorySize, S_TOTAL);

    prep_B<<<1, 256>>>(Wc);

    dim3 grid(Hh / 2, Bn);   // (row-pair, batch): 1024 CTAs x 256 threads
    convlstm_hmma<true><<<grid, NT, S_TOTAL>>>(X, bc, out, 0);
    for (int t = 1; t < SEQ; t++) {
        convlstm_hmma<false><<<grid, NT, S_TOTAL>>>(X, bc, out, t);
    }
}

// round 13
// speedup vs baseline: 3.2536x; 1.3311x over previous
#include <cuda_runtime.h>
#include <cuda_fp16.h>
#include <math.h>
#include <stdint.h>

// Problem constants
#define Bn    16
#define CINc  8
#define SEQ   32
#define Hh    128
#define Ww    128
#define COUTc 8
#define ZC    32      // 4*COUT gate channels (N)
#define CTOT  16      // CIN + COUT
#define KTOT  144     // 9 taps * 16 channels (K); k = tap*16 + c

#define NT    256     // 8 warps; warp w: output row yl=w>>2, x0=(w&3)*32
#define XPU   136     // strip row pitch in u32 (f16x2); left pad 1, conflict-free
#define NPP   32      // 4 y-rows x 8 channel-pairs

// dynamic smem layout (bytes)
#define S_XH   0
#define S_XL   (NPP * XPU * 4)          // 17408
#define S_B2H  (2 * NPP * XPU * 4)      // 34816
#define S_B2L  (S_B2H + 9 * 4 * 32 * 8) // +9216 = 44032
#define S_BIAS (S_B2L + 9 * 4 * 32 * 8) // 53248
#define S_TOTAL (S_BIAS + 128)          // 53376

#define STATE_ELEMS (Bn * COUTc * Hh * Ww)
__device__ float g_h[2][STATE_ELEMS];   // ping-pong h (cross-block halo safety)
__device__ float g_c[STATE_ELEMS];
// B operands: [tap][nt][lane] -> uint2 {b0, b1} (hi and lo splits)
__device__ __align__(16) uint2 g_B2h[9 * 4 * 32];
__device__ __align__(16) uint2 g_B2l[9 * 4 * 32];

__device__ __forceinline__ float sigf(float x) {
    return __fdividef(1.0f, 1.0f + __expf(-x));
}
__device__ __forceinline__ float tanhfast(float x) {
    return __fdividef(2.0f, 1.0f + __expf(-2.0f * x)) - 1.0f;
}

// pack two f32 into f16x2 (lo half = v0) and the f16x2 residual pack
__device__ __forceinline__ void pack_split(float v0, float v1,
                                           uint32_t& hi, uint32_t& lo) {
    asm("cvt.rn.f16x2.f32 %0, %1, %2;" : "=r"(hi) : "f"(v1), "f"(v0));
    float h0, h1;
    asm("{ .reg .b16 l,h; mov.b32 {l,h}, %2; cvt.f32.f16 %0, l; cvt.f32.f16 %1, h; }"
        : "=f"(h0), "=f"(h1) : "r"(hi));
    float r0 = v0 - h0, r1 = v1 - h1;
    asm("cvt.rn.f16x2.f32 %0, %1, %2;" : "=r"(lo) : "f"(r1), "f"(r0));
}

__device__ __forceinline__ void mma16816(float* d, const uint32_t* a,
                                         uint32_t b0, uint32_t b1) {
    asm volatile(
        "mma.sync.aligned.m16n8k16.row.col.f32.f16.f16.f32 "
        "{%0,%1,%2,%3}, {%4,%5,%6,%7}, {%8,%9}, {%0,%1,%2,%3};"
        : "+f"(d[0]), "+f"(d[1]), "+f"(d[2]), "+f"(d[3])
        : "r"(a[0]), "r"(a[1]), "r"(a[2]), "r"(a[3]), "r"(b0), "r"(b1));
}

// ---- prep: B fragment pairs per (tap, nt, lane); n = nt*8+g, c0 = tg*2
// B[n][k] = Wc[n*144 + c*9 + tap], k = tap*16 + c
__global__ void prep_B(const float* __restrict__ Wc) {
    for (int i = threadIdx.x; i < 9 * 4 * 32; i += blockDim.x) {
        int lane = i & 31;
        int nt   = (i >> 5) & 3;
        int tap  = i / 128;
        int g2   = lane >> 2;
        int tg   = lane & 3;
        int n    = nt * 8 + g2;
        int c0   = tg * 2;
        float w00 = Wc[n * KTOT + (c0    ) * 9 + tap];
        float w01 = Wc[n * KTOT + (c0 + 1) * 9 + tap];
        float w10 = Wc[n * KTOT + (c0 + 8) * 9 + tap];
        float w11 = Wc[n * KTOT + (c0 + 9) * 9 + tap];
        uint32_t h0, l0, h1, l1;
        pack_split(w00, w01, h0, l0);
        pack_split(w10, w11, h1, l1);
        g_B2h[i] = make_uint2(h0, h1);
        g_B2l[i] = make_uint2(l0, l1);
    }
}

// ---- main: one CTA = TWO image rows (M=256 px) x N=32 x K=144 ----
template <bool FIRST>
__global__ __launch_bounds__(NT, 4)
void convlstm_hmma(const float* __restrict__ X,
                   const float* __restrict__ bc,
                   float* __restrict__ out,
                   int t)
{
    extern __shared__ __align__(16) char smem[];
    uint32_t* s_xh  = reinterpret_cast<uint32_t*>(smem + S_XH);
    uint32_t* s_xl  = reinterpret_cast<uint32_t*>(smem + S_XL);
    uint2*    s_b2h = reinterpret_cast<uint2*>(smem + S_B2H);
    uint2*    s_b2l = reinterpret_cast<uint2*>(smem + S_B2L);
    float*    s_bias = reinterpret_cast<float*>(smem + S_BIAS);

    const int tid  = threadIdx.x;
    const int w    = tid >> 5;
    const int lane = tid & 31;
    const int g    = lane >> 2;   // fragment row within tile
    const int tg   = lane & 3;    // fragment k-col pair
    const int yl   = w >> 2;      // 0/1: which output row of the pair
    const int x0   = (w & 3) * 32;
    const int y0 = blockIdx.x * 2, b = blockIdx.y;

    const float* __restrict__ h_prev = g_h[(t + 1) & 1];
    float* __restrict__ h_cur = g_h[t & 1];

    // zero packed strips (both splits)
    {
        uint4 z4 = make_uint4(0u, 0u, 0u, 0u);
        uint4* p = reinterpret_cast<uint4*>(smem);
        for (int i = tid; i < (2 * NPP * XPU) / 4; i += NT) p[i] = z4;
    }
    // copy B pairs
    {
        const uint4* sh = reinterpret_cast<const uint4*>(g_B2h);
        const uint4* sl = reinterpret_cast<const uint4*>(g_B2l);
        uint4* dh = reinterpret_cast<uint4*>(s_b2h);
        uint4* dl = reinterpret_cast<uint4*>(s_b2l);
        for (int i = tid; i < (9 * 4 * 32 * 8) / 16; i += NT) { dh[i] = sh[i]; dl[i] = sl[i]; }
    }
    if (tid < ZC) s_bias[tid] = bc[tid];
    __syncthreads();

    // fill strip: pair-plane p = r*8 + cp (r=0..3 -> gy=y0+r-1; cp=ch pair)
    // pack f16 split at load time; fp32 strip never materialized.
    // input x = xi goes to strip col xi+1 (col 0 = left zero pad).
    for (int i = tid; i < NPP * 128; i += NT) {
        int p  = i >> 7;
        int xi = i & 127;
        int r  = p >> 3;
        int cp = p & 7;
        int gy = y0 + r - 1;
        if (gy >= 0 && gy < Hh) {
            int c = cp * 2;
            float v0, v1;
            if (c < CINc) {
                size_t base = (((size_t)(b * CINc + c) * SEQ + t) * Hh + gy) * Ww + xi;
                v0 = X[base];
                v1 = X[base + (size_t)SEQ * Hh * Ww];
            } else if (!FIRST) {
                size_t base = ((size_t)(b * COUTc + (c - CINc)) * Hh + gy) * Ww + xi;
                v0 = h_prev[base];
                v1 = h_prev[base + (size_t)Hh * Ww];
            } else {
                continue;
            }
            uint32_t hi, lo;
            pack_split(v0, v1, hi, lo);
            s_xh[p * XPU + xi + 1] = hi;
            s_xl[p * XPU + xi + 1] = lo;
        }
    }
    __syncthreads();

    // accumulators: [m-tile][n-tile][frag reg]
    float d[2][4][4];
#pragma unroll
    for (int mt = 0; mt < 2; mt++)
#pragma unroll
        for (int nt = 0; nt < 4; nt++)
#pragma unroll
            for (int r = 0; r < 4; r++) d[mt][nt][r] = 0.0f;

#pragma unroll 1
    for (int tap = 0; tap < 9; tap++) {
        const int ky = tap / 3;
        const int kx = tap - ky * 3;
        // A base: pair-plane (yl+ky)*8 + tg.
        // For output pixel P, tap kx: input x = P+kx-1 -> strip col P+kx
        // (pad already absorbed). P for a0 = x0 + g, so col = x0 + g + kx.
        const int xoff = ((yl + ky) * 8 + tg) * XPU + (x0 + g + kx);
        const uint32_t* xh = s_xh + xoff;
        const uint32_t* xl = s_xl + xoff;

        uint32_t ah[2][4], al[2][4];
#pragma unroll
        for (int mt = 0; mt < 2; mt++) {
            const int m16 = mt * 16;
            ah[mt][0] = xh[m16];               al[mt][0] = xl[m16];
            ah[mt][1] = xh[m16 + 8];           al[mt][1] = xl[m16 + 8];
            ah[mt][2] = xh[4 * XPU + m16];     al[mt][2] = xl[4 * XPU + m16];
            ah[mt][3] = xh[4 * XPU + m16 + 8]; al[mt][3] = xl[4 * XPU + m16 + 8];
        }

#pragma unroll
        for (int nt = 0; nt < 4; nt++) {
            const int bi = (tap * 4 + nt) * 32 + lane;
            uint2 bh = s_b2h[bi];
            uint2 bl = s_b2l[bi];
#pragma unroll
            for (int mt = 0; mt < 2; mt++) {
                mma16816(d[mt][nt], ah[mt], bh.x, bh.y);  // Ah*Bh
                mma16816(d[mt][nt], al[mt], bh.x, bh.y);  // Al*Bh
                mma16816(d[mt][nt], ah[mt], bl.x, bl.y);  // Ah*Bl
            }
        }
    }

    // ---- epilogue: gates + state + output ----
    const int y = y0 + yl;
#pragma unroll
    for (int mt = 0; mt < 2; mt++) {
#pragma unroll
        for (int rs = 0; rs < 2; rs++) {
            const int x = x0 + mt * 16 + rs * 8 + g;
#pragma unroll
            for (int e = 0; e < 2; e++) {
                const int ch = tg * 2 + e;
                const int ri = rs * 2 + e;
                float zi = d[mt][0][ri] + s_bias[ch];
                float zf = d[mt][1][ri] + s_bias[8 + ch];
                float zg = d[mt][2][ri] + s_bias[16 + ch];
                float zo = d[mt][3][ri] + s_bias[24 + ch];

                float ig = sigf(zi);
                float fg = sigf(zf);
                float gg = tanhfast(zg);
                float og = sigf(zo);

                size_t sidx = ((size_t)(b * COUTc + ch) * Hh + y) * Ww + x;
                float cp = FIRST ? 0.0f : g_c[sidx];
                float cn = fg * cp + ig * gg;
                float hn = og * tanhfast(cn);
                g_c[sidx] = cn;
                h_cur[sidx] = hn;
                out[((size_t)(b * COUTc + ch) * SEQ + t) * (Hh * Ww)
                    + (size_t)y * Ww + x] = hn;
            }
        }
    }
}

extern "C" void kernel_launch(void* const* d_in, const int* in_sizes, int n_in,
                              void* d_out, int out_size)
{
    const float* X  = (const float*)d_in[0];
    const float* Wc = (const float*)d_in[1];
    const float* bc = (const float*)d_in[2];
    float* out = (float*)d_out;

    cudaFuncSetAttribute(convlstm_hmma<true>,
                         cudaFuncAttributeMaxDynamicSharedMemorySize, S_TOTAL);
    cudaFuncSetAttribute(convlstm_hmma<false>,
                         cudaFuncAttributeMaxDynamicSharedMemorySize, S_TOTAL);

    prep_B<<<1, 256>>>(Wc);

    dim3 grid(Hh / 2, Bn);   // (row-pair, batch): 1024 CTAs x 256 threads
    convlstm_hmma<true><<<grid, NT, S_TOTAL>>>(X, bc, out, 0);
    for (int t = 1; t < SEQ; t++) {
        convlstm_hmma<false><<<grid, NT, S_TOTAL>>>(X, bc, out, t);
    }
}

// round 14
// speedup vs baseline: 4.3825x; 1.3470x over previous
#include <cuda_runtime.h>
#include <cuda_fp16.h>
#include <math.h>
#include <stdint.h>

// Problem constants
#define Bn    16
#define CINc  8
#define SEQ   32
#define Hh    128
#define Ww    128
#define COUTc 8
#define ZC    32      // 4*COUT gate channels (N)
#define CTOT  16      // CIN + COUT
#define KTOT  144     // 9 taps * 16 channels (K); k = tap*16 + c

#define NT    256     // 8 warps; warp w: output row yl=w>>2, x0=(w&3)*32
#define XPU   136     // strip row pitch in u32 (f16x2); left pad 1, conflict-free
#define NPP   32      // 4 y-rows x 8 channel-pairs

// dynamic smem layout (bytes)
#define S_XH   0
#define S_XL   (NPP * XPU * 4)          // 17408
#define S_B2H  (2 * NPP * XPU * 4)      // 34816
#define S_B2L  (S_B2H + 9 * 4 * 32 * 8) // +9216 = 44032
#define S_BIAS (S_B2L + 9 * 4 * 32 * 8) // 53248
#define S_TOTAL (S_BIAS + 128)          // 53376

#define STATE_ELEMS (Bn * COUTc * Hh * Ww)
__device__ float g_h[2][STATE_ELEMS];   // ping-pong h (cross-block halo safety)
__device__ float g_c[STATE_ELEMS];
// B operands: [tap][nt][lane] -> uint2 {b0, b1} (hi and lo splits)
__device__ __align__(16) uint2 g_B2h[9 * 4 * 32];
__device__ __align__(16) uint2 g_B2l[9 * 4 * 32];

__device__ __forceinline__ float sigf(float x) {
    return __fdividef(1.0f, 1.0f + __expf(-x));
}
__device__ __forceinline__ float tanhfast(float x) {
    return __fdividef(2.0f, 1.0f + __expf(-2.0f * x)) - 1.0f;
}

// pack two f32 into f16x2 (lo half = v0) and the f16x2 residual pack
__device__ __forceinline__ void pack_split(float v0, float v1,
                                           uint32_t& hi, uint32_t& lo) {
    asm("cvt.rn.f16x2.f32 %0, %1, %2;" : "=r"(hi) : "f"(v1), "f"(v0));
    float h0, h1;
    asm("{ .reg .b16 l,h; mov.b32 {l,h}, %2; cvt.f32.f16 %0, l; cvt.f32.f16 %1, h; }"
        : "=f"(h0), "=f"(h1) : "r"(hi));
    float r0 = v0 - h0, r1 = v1 - h1;
    asm("cvt.rn.f16x2.f32 %0, %1, %2;" : "=r"(lo) : "f"(r1), "f"(r0));
}

__device__ __forceinline__ void mma16816(float* d, const uint32_t* a,
                                         uint32_t b0, uint32_t b1) {
    asm volatile(
        "mma.sync.aligned.m16n8k16.row.col.f32.f16.f16.f32 "
        "{%0,%1,%2,%3}, {%4,%5,%6,%7}, {%8,%9}, {%0,%1,%2,%3};"
        : "+f"(d[0]), "+f"(d[1]), "+f"(d[2]), "+f"(d[3])
        : "r"(a[0]), "r"(a[1]), "r"(a[2]), "r"(a[3]), "r"(b0), "r"(b1));
}

// ---- prep: B fragment pairs per (tap, nt, lane); n = nt*8+g, c0 = tg*2
// B[n][k] = Wc[n*144 + c*9 + tap], k = tap*16 + c
__global__ void prep_B(const float* __restrict__ Wc) {
    for (int i = threadIdx.x; i < 9 * 4 * 32; i += blockDim.x) {
        int lane = i & 31;
        int nt   = (i >> 5) & 3;
        int tap  = i / 128;
        int g2   = lane >> 2;
        int tg   = lane & 3;
        int n    = nt * 8 + g2;
        int c0   = tg * 2;
        float w00 = Wc[n * KTOT + (c0    ) * 9 + tap];
        float w01 = Wc[n * KTOT + (c0 + 1) * 9 + tap];
        float w10 = Wc[n * KTOT + (c0 + 8) * 9 + tap];
        float w11 = Wc[n * KTOT + (c0 + 9) * 9 + tap];
        uint32_t h0, l0, h1, l1;
        pack_split(w00, w01, h0, l0);
        pack_split(w10, w11, h1, l1);
        g_B2h[i] = make_uint2(h0, h1);
        g_B2l[i] = make_uint2(l0, l1);
    }
}

// ---- main: one CTA = TWO image rows (M=256 px) x N=32 x K=144 ----
template <bool FIRST>
__global__ __launch_bounds__(NT, 4)
void convlstm_hmma(const float* __restrict__ X,
                   const float* __restrict__ bc,
                   float* __restrict__ out,
                   int t)
{
    extern __shared__ __align__(16) char smem[];
    uint32_t* s_xh  = reinterpret_cast<uint32_t*>(smem + S_XH);
    uint32_t* s_xl  = reinterpret_cast<uint32_t*>(smem + S_XL);
    uint2*    s_b2h = reinterpret_cast<uint2*>(smem + S_B2H);
    uint2*    s_b2l = reinterpret_cast<uint2*>(smem + S_B2L);
    float*    s_bias = reinterpret_cast<float*>(smem + S_BIAS);

    const int tid  = threadIdx.x;
    const int w    = tid >> 5;
    const int lane = tid & 31;
    const int g    = lane >> 2;   // fragment row within tile
    const int tg   = lane & 3;    // fragment k-col pair
    const int yl   = w >> 2;      // 0/1: which output row of the pair
    const int x0   = (w & 3) * 32;
    const int y0 = blockIdx.x * 2, b = blockIdx.y;

    const float* __restrict__ h_prev = g_h[(t + 1) & 1];
    float* __restrict__ h_cur = g_h[t & 1];

    // zero only the pad columns actually read: col 0 and col 129, both splits
    if (tid < 2 * NPP * 2) {
        int p     = tid >> 2;
        int r     = tid & 3;
        int col   = (r & 1) ? 129 : 0;
        uint32_t* s = (r >> 1) ? s_xl : s_xh;
        s[p * XPU + col] = 0u;
    }
    // copy B pairs
    {
        const uint4* sh = reinterpret_cast<const uint4*>(g_B2h);
        const uint4* sl = reinterpret_cast<const uint4*>(g_B2l);
        uint4* dh = reinterpret_cast<uint4*>(s_b2h);
        uint4* dl = reinterpret_cast<uint4*>(s_b2l);
        for (int i = tid; i < (9 * 4 * 32 * 8) / 16; i += NT) { dh[i] = sh[i]; dl[i] = sl[i]; }
    }
    if (tid < ZC) s_bias[tid] = bc[tid];

    // fill strip (vectorized float4): pair-plane p = r*8 + cp; always stores
    // (zeros when out of range / FIRST h), so no bulk zero pass needed.
    // input x = xi -> strip col xi+1.
    for (int i = tid; i < NPP * 32; i += NT) {
        int p  = i >> 5;
        int x4 = (i & 31) * 4;    // xi base (0..124, step 4)
        int r  = p >> 3;
        int cp = p & 7;
        int gy = y0 + r - 1;
        int c  = cp * 2;
        float4 a0 = make_float4(0.f, 0.f, 0.f, 0.f);
        float4 a1 = a0;
        if (gy >= 0 && gy < Hh) {
            if (c < CINc) {
                size_t base = (((size_t)(b * CINc + c) * SEQ + t) * Hh + gy) * Ww + x4;
                a0 = *reinterpret_cast<const float4*>(X + base);
                a1 = *reinterpret_cast<const float4*>(X + base + (size_t)SEQ * Hh * Ww);
            } else if (!FIRST) {
                size_t base = ((size_t)(b * COUTc + (c - CINc)) * Hh + gy) * Ww + x4;
                a0 = *reinterpret_cast<const float4*>(h_prev + base);
                a1 = *reinterpret_cast<const float4*>(h_prev + base + (size_t)Hh * Ww);
            }
        }
        uint32_t hi, lo;
        const int o = p * XPU + x4 + 1;
        pack_split(a0.x, a1.x, hi, lo); s_xh[o]     = hi; s_xl[o]     = lo;
        pack_split(a0.y, a1.y, hi, lo); s_xh[o + 1] = hi; s_xl[o + 1] = lo;
        pack_split(a0.z, a1.z, hi, lo); s_xh[o + 2] = hi; s_xl[o + 2] = lo;
        pack_split(a0.w, a1.w, hi, lo); s_xh[o + 3] = hi; s_xl[o + 3] = lo;
    }
    __syncthreads();

    // accumulators: [m-tile][n-tile][frag reg]
    float d[2][4][4];
#pragma unroll
    for (int mt = 0; mt < 2; mt++)
#pragma unroll
        for (int nt = 0; nt < 4; nt++)
#pragma unroll
            for (int r = 0; r < 4; r++) d[mt][nt][r] = 0.0f;

#pragma unroll
    for (int tap = 0; tap < 9; tap++) {
        const int ky = tap / 3;
        const int kx = tap - ky * 3;
        // A base: pair-plane (yl+ky)*8 + tg; col = x0 + g + kx (pad absorbed).
        const int xoff = ((yl + ky) * 8 + tg) * XPU + (x0 + g + kx);
        const uint32_t* xh = s_xh + xoff;
        const uint32_t* xl = s_xl + xoff;

        uint32_t ah[2][4], al[2][4];
#pragma unroll
        for (int mt = 0; mt < 2; mt++) {
            const int m16 = mt * 16;
            ah[mt][0] = xh[m16];               al[mt][0] = xl[m16];
            ah[mt][1] = xh[m16 + 8];           al[mt][1] = xl[m16 + 8];
            ah[mt][2] = xh[4 * XPU + m16];     al[mt][2] = xl[4 * XPU + m16];
            ah[mt][3] = xh[4 * XPU + m16 + 8]; al[mt][3] = xl[4 * XPU + m16 + 8];
        }

#pragma unroll
        for (int nt = 0; nt < 4; nt++) {
            const int bi = (tap * 4 + nt) * 32 + lane;
            uint2 bh = s_b2h[bi];
            uint2 bl = s_b2l[bi];
#pragma unroll
            for (int mt = 0; mt < 2; mt++) {
                mma16816(d[mt][nt], ah[mt], bh.x, bh.y);  // Ah*Bh
                mma16816(d[mt][nt], al[mt], bh.x, bh.y);  // Al*Bh
                mma16816(d[mt][nt], ah[mt], bl.x, bl.y);  // Ah*Bl
            }
        }
    }

    // ---- epilogue: gates + state + output ----
    const int y = y0 + yl;
#pragma unroll
    for (int mt = 0; mt < 2; mt++) {
#pragma unroll
        for (int rs = 0; rs < 2; rs++) {
            const int x = x0 + mt * 16 + rs * 8 + g;
#pragma unroll
            for (int e = 0; e < 2; e++) {
                const int ch = tg * 2 + e;
                const int ri = rs * 2 + e;
                float zi = d[mt][0][ri] + s_bias[ch];
                float zf = d[mt][1][ri] + s_bias[8 + ch];
                float zg = d[mt][2][ri] + s_bias[16 + ch];
                float zo = d[mt][3][ri] + s_bias[24 + ch];

                float ig = sigf(zi);
                float fg = sigf(zf);
                float gg = tanhfast(zg);
                float og = sigf(zo);

                size_t sidx = ((size_t)(b * COUTc + ch) * Hh + y) * Ww + x;
                float cp = FIRST ? 0.0f : g_c[sidx];
                float cn = fg * cp + ig * gg;
                float hn = og * tanhfast(cn);
                g_c[sidx] = cn;
                h_cur[sidx] = hn;
                out[((size_t)(b * COUTc + ch) * SEQ + t) * (Hh * Ww)
                    + (size_t)y * Ww + x] = hn;
            }
        }
    }
}

extern "C" void kernel_launch(void* const* d_in, const int* in_sizes, int n_in,
                              void* d_out, int out_size)
{
    const float* X  = (const float*)d_in[0];
    const float* Wc = (const float*)d_in[1];
    const float* bc = (const float*)d_in[2];
    float* out = (float*)d_out;

    cudaFuncSetAttribute(convlstm_hmma<true>,
                         cudaFuncAttributeMaxDynamicSharedMemorySize, S_TOTAL);
    cudaFuncSetAttribute(convlstm_hmma<false>,
                         cudaFuncAttributeMaxDynamicSharedMemorySize, S_TOTAL);

    prep_B<<<1, 256>>>(Wc);

    dim3 grid(Hh / 2, Bn);   // (row-pair, batch): 1024 CTAs x 256 threads
    convlstm_hmma<true><<<grid, NT, S_TOTAL>>>(X, bc, out, 0);
    for (int t = 1; t < SEQ; t++) {
        convlstm_hmma<false><<<grid, NT, S_TOTAL>>>(X, bc, out, t);
    }
}